// round 12
// baseline (speedup 1.0000x reference)
#include <cuda_runtime.h>
#include <cuda_fp16.h>
#include <cuda_bf16.h>
#include <math_constants.h>

#define NN 50000
#define EE 800000
#define ETOT (EE + NN)
#define EMB_DIM 8
#define FEAT_DIM 15
#define GAT_IN 23
#define CAP 64
#define FULL 0xffffffffu

// Scratch (__device__ globals) — feature tensors fp16-packed (uint2 = 4 halves)
__device__ uint2  g_h2[NN * 32];      // h (post-GEMM messages)
__device__ uint2  g_xB2[NN * 32];     // activations ping
__device__ uint2  g_xC2[NN * 32];     // activations pong
__device__ float4 g_as4[NN];          // alpha_src (up to 4 heads, fp32)
__device__ float4 g_ad4[NN];          // alpha_dst
__device__ int   g_count[NN];
__device__ int   g_esrc[NN * CAP];

__device__ __forceinline__ float leaky(float v) {
    return v > 0.0f ? v : 0.2f * v;
}

__device__ __forceinline__ uint2 pack_h4(float4 a) {
    __half2 lo = __floats2half2_rn(a.x, a.y);
    __half2 hi = __floats2half2_rn(a.z, a.w);
    return make_uint2(*(unsigned*)&lo, *(unsigned*)&hi);
}

__device__ __forceinline__ float4 unpack_h4(uint2 pk) {
    __half2 lo = *(__half2*)&pk.x;
    __half2 hi = *(__half2*)&pk.y;
    float2 f0 = __half22float2(lo);
    float2 f1 = __half22float2(hi);
    return make_float4(f0.x, f0.y, f1.x, f1.y);
}

__device__ __forceinline__ void unpack_fma(uint2 pk, float exj, float4& acc) {
    float4 f = unpack_h4(pk);
    acc.x = fmaf(exj, f.x, acc.x);
    acc.y = fmaf(exj, f.y, acc.y);
    acc.z = fmaf(exj, f.z, acc.z);
    acc.w = fmaf(exj, f.w, acc.w);
}

// ---- packed f32x2 helpers (SASS FFMA2; PTX-only on sm_103a) ----
__device__ __forceinline__ unsigned long long pk2(float a, float b) {
    unsigned long long r;
    asm("mov.b64 %0, {%1, %2};" : "=l"(r) : "f"(a), "f"(b));
    return r;
}
__device__ __forceinline__ void ffma2(unsigned long long& d,
                                      unsigned long long a,
                                      unsigned long long b) {
    asm("fma.rn.f32x2 %0, %1, %2, %0;" : "+l"(d) : "l"(a), "l"(b));
}
__device__ __forceinline__ float2 unpk2(unsigned long long v) {
    float2 r;
    asm("mov.b64 {%0, %1}, %2;" : "=f"(r.x), "=f"(r.y) : "l"(v));
    return r;
}

// ===========================================================================
// One-pass slot-CSR (ILP 8 to overlap ATOMG latency chains).
// ===========================================================================
__global__ void k_scatter(const int* __restrict__ src,
                          const int* __restrict__ dst, int E, int Etot, int T,
                          int* __restrict__ count, int* __restrict__ esrc) {
    const int g = blockIdx.x * blockDim.x + threadIdx.x;
#pragma unroll
    for (int k = 0; k < 8; k++) {
        int e = g + k * T;
        if (e < Etot) {
            int s, d;
            if (e < E) { s = __ldg(&src[e]); d = __ldg(&dst[e]); }
            else       { s = d = e - E; }
            int pos = atomicAdd(&count[d], 1);
            esrc[(d << 6) + pos] = s;
        }
    }
}

// ===========================================================================
// Layer-1 GEMM: 256 thr, NT=64 nodes/block, NR=8, FFMA2 inner loop.
// ===========================================================================
__global__ void k_mm1(const int* __restrict__ node_ids,
                      const float* __restrict__ feats,
                      const float* __restrict__ emb,
                      const float4* __restrict__ W4,
                      const float4* __restrict__ asw4,
                      const float4* __restrict__ adw4,
                      uint2* __restrict__ h2,
                      float* __restrict__ as_o, float* __restrict__ ad_o) {
    constexpr int QC = 32, TY = 8, NR = 8, NT = 64;
    __shared__ float4 Ws4[GAT_IN * QC];
    __shared__ float xs[NT * 33];

    const int tid = threadIdx.x;
    const int tx = tid & 31;
    const int ty = tid >> 5;
    const int blockBase = blockIdx.x * NT;

    for (int i = tid; i < GAT_IN * QC; i += 256)
        Ws4[i] = W4[i];

    for (int i = tid; i < NT * 32; i += 256) {
        int l = i >> 5;
        int k = i & 31;
        int n = blockBase + l;
        float v = 0.0f;
        if (n < NN && k < GAT_IN) {
            if (k < EMB_DIM) v = emb[__ldg(&node_ids[n]) * EMB_DIM + k];
            else             v = feats[n * FEAT_DIM + (k - EMB_DIM)];
        }
        xs[l * 33 + k] = v;
    }
    __syncthreads();

    unsigned long long accL[NR], accH[NR];
#pragma unroll
    for (int r = 0; r < NR; r++) { accL[r] = pk2(0.f, 0.f); accH[r] = pk2(0.f, 0.f); }

#pragma unroll
    for (int k = 0; k < GAT_IN; k++) {
        ulonglong2 w2 = *reinterpret_cast<const ulonglong2*>(&Ws4[k * QC + tx]);
#pragma unroll
        for (int r = 0; r < NR; r++) {
            float xv = xs[(ty + TY * r) * 33 + k];
            unsigned long long xx = pk2(xv, xv);
            ffma2(accL[r], xx, w2.x);
            ffma2(accH[r], xx, w2.y);
        }
    }

    const float4 aw = __ldg(&asw4[tx]);
    const float4 dw = __ldg(&adw4[tx]);
#pragma unroll
    for (int r = 0; r < NR; r++) {
        int n = blockBase + ty + TY * r;
        float2 lo = unpk2(accL[r]);
        float2 hi = unpk2(accH[r]);
        float4 acc = make_float4(lo.x, lo.y, hi.x, hi.y);
        float s = acc.x * aw.x + acc.y * aw.y + acc.z * aw.z + acc.w * aw.w;
        float d = acc.x * dw.x + acc.y * dw.y + acc.z * dw.z + acc.w * dw.w;
#pragma unroll
        for (int off = 4; off > 0; off >>= 1) {
            s += __shfl_down_sync(FULL, s, off, 8);
            d += __shfl_down_sync(FULL, d, off, 8);
        }
        if (n < NN) {
            h2[n * QC + tx] = pack_h4(acc);
            if ((tx & 7) == 0) {
                int head = tx >> 3;
                as_o[n * 4 + head] = s;
                ad_o[n * 4 + head] = d;
            }
        }
    }
}

// ===========================================================================
// Register-tiled GEMM (layers 2-4): NB threads, NR nodes x 4 chans each,
// FFMA2 inner loop; KT chosen to minimize barrier count.
// ===========================================================================
template <int FIN, int H, int C, int NR, int NB, int KT>
__global__ void __launch_bounds__(NB)
k_mmt(const uint2* __restrict__ x2,
      const float4* __restrict__ W4,
      const float4* __restrict__ asw4,
      const float4* __restrict__ adw4,
      uint2* __restrict__ h2,
      float* __restrict__ as_o, float* __restrict__ ad_o) {
    constexpr int HC = H * C;
    constexpr int QC = HC / 4;
    constexpr int TY = NB / QC;
    constexpr int NT = TY * NR;
    constexpr int K4 = KT / 4;
    constexpr int QF = FIN / 4;
    constexpr int GPH = C / 4;

    __shared__ float4 Ws4[FIN * QC];
    __shared__ float4 xs4[NT][K4 + 1];

    const int tid = threadIdx.x;
    const int tx = tid % QC;
    const int ty = tid / QC;
    const int blockBase = blockIdx.x * NT;

    for (int i = tid; i < FIN * QC; i += NB)
        Ws4[i] = W4[i];

    unsigned long long accL[NR], accH[NR];
#pragma unroll
    for (int r = 0; r < NR; r++) { accL[r] = pk2(0.f, 0.f); accH[r] = pk2(0.f, 0.f); }

    for (int kb = 0; kb < FIN; kb += KT) {
        __syncthreads();
        for (int i = tid; i < NT * K4; i += NB) {
            int l = i / K4;
            int c4 = i % K4;
            int n = blockBase + l;
            xs4[l][c4] = (n < NN) ? unpack_h4(x2[n * QF + kb / 4 + c4])
                                  : make_float4(0.f, 0.f, 0.f, 0.f);
        }
        __syncthreads();
#pragma unroll
        for (int k4 = 0; k4 < K4; k4++) {
            float4 xv[NR];
#pragma unroll
            for (int r = 0; r < NR; r++)
                xv[r] = xs4[ty + TY * r][k4];
#pragma unroll
            for (int kk = 0; kk < 4; kk++) {
                ulonglong2 w2 = *reinterpret_cast<const ulonglong2*>(
                    &Ws4[(kb + k4 * 4 + kk) * QC + tx]);
#pragma unroll
                for (int r = 0; r < NR; r++) {
                    float xvk = (kk == 0) ? xv[r].x : (kk == 1) ? xv[r].y
                              : (kk == 2) ? xv[r].z : xv[r].w;
                    unsigned long long xx = pk2(xvk, xvk);
                    ffma2(accL[r], xx, w2.x);
                    ffma2(accH[r], xx, w2.y);
                }
            }
        }
    }

    const float4 aw = __ldg(&asw4[tx]);
    const float4 dw = __ldg(&adw4[tx]);
#pragma unroll
    for (int r = 0; r < NR; r++) {
        int n = blockBase + ty + TY * r;
        float2 lo = unpk2(accL[r]);
        float2 hi = unpk2(accH[r]);
        float4 acc = make_float4(lo.x, lo.y, hi.x, hi.y);
        float s = acc.x * aw.x + acc.y * aw.y + acc.z * aw.z + acc.w * aw.w;
        float d = acc.x * dw.x + acc.y * dw.y + acc.z * dw.z + acc.w * dw.w;
#pragma unroll
        for (int off = GPH / 2; off > 0; off >>= 1) {
            s += __shfl_down_sync(FULL, s, off, GPH);
            d += __shfl_down_sync(FULL, d, off, GPH);
        }
        if (n < NN) {
            h2[n * QC + tx] = pack_h4(acc);
            if ((tx % GPH) == 0) {
                int head = tx / GPH;
                as_o[n * H + head] = s;
                ad_o[n * H + head] = d;
            }
        }
    }
}

// ===========================================================================
// Aggregation H=4, C=32: warp per node, single pass, fp16 h gather + fp16 out.
// ===========================================================================
__global__ void k_agg4(const int* __restrict__ count,
                       const int* __restrict__ esrc,
                       const float4* __restrict__ as4,
                       const float4* __restrict__ ad4,
                       const uint2* __restrict__ h2,
                       const float4* __restrict__ b4,
                       uint2* __restrict__ out2) {
    __shared__ float4 sEx[8][32];
    __shared__ int sSj[8][32];
    const int n = (blockIdx.x * blockDim.x + threadIdx.x) >> 5;
    const int w = (threadIdx.x >> 5);
    const int lane = threadIdx.x & 31;
    if (n >= NN) return;
    const int hd = lane >> 3;

    const int beg = n << 6;
    const int end = beg + count[n];
    const float4 adn = __ldg(&ad4[n]);

    float4 acc = make_float4(0.f, 0.f, 0.f, 0.f);
    float4 dsum = make_float4(0.f, 0.f, 0.f, 0.f);

    for (int base = beg; base < end; base += 32) {
        const int e = base + lane;
        float4 ex = make_float4(0.f, 0.f, 0.f, 0.f);
        int s = 0;
        if (e < end) {
            s = esrc[e];
            float4 a = __ldg(&as4[s]);
            ex.x = __expf(leaky(a.x + adn.x));
            ex.y = __expf(leaky(a.y + adn.y));
            ex.z = __expf(leaky(a.z + adn.z));
            ex.w = __expf(leaky(a.w + adn.w));
        }
        dsum.x += ex.x; dsum.y += ex.y; dsum.z += ex.z; dsum.w += ex.w;
        __syncwarp();
        sEx[w][lane] = ex;
        sSj[w][lane] = s;
        __syncwarp();
        const int cnt = min(32, end - base);
#pragma unroll 2
        for (int j = 0; j < cnt; j++) {
            int sj = sSj[w][j];
            float exj = ((const float*)&sEx[w][j])[hd];
            uint2 pk = h2[sj * 32 + lane];
            unpack_fma(pk, exj, acc);
        }
    }

#pragma unroll
    for (int off = 16; off > 0; off >>= 1) {
        dsum.x += __shfl_xor_sync(FULL, dsum.x, off);
        dsum.y += __shfl_xor_sync(FULL, dsum.y, off);
        dsum.z += __shfl_xor_sync(FULL, dsum.z, off);
        dsum.w += __shfl_xor_sync(FULL, dsum.w, off);
    }
    float den = (hd == 0) ? dsum.x : (hd == 1) ? dsum.y : (hd == 2) ? dsum.z : dsum.w;
    float inv = 1.0f / (den + 1e-16f);
    float4 bb = __ldg(&b4[lane]);
    float4 o;
    o.x = fmaxf(acc.x * inv + bb.x, 0.f);
    o.y = fmaxf(acc.y * inv + bb.y, 0.f);
    o.z = fmaxf(acc.z * inv + bb.z, 0.f);
    o.w = fmaxf(acc.w * inv + bb.w, 0.f);
    out2[n * 32 + lane] = pack_h4(o);
}

// ===========================================================================
// Aggregation H=1: warp per node; OUTH=1 -> fp16 out, else fp32 out.
// ===========================================================================
template <int C, int ACT, int OUTH>
__global__ void k_agg1(const int* __restrict__ count,
                       const int* __restrict__ esrc,
                       const float* __restrict__ as,
                       const float* __restrict__ ad,
                       const uint2* __restrict__ h2,
                       const float4* __restrict__ b4,
                       void* __restrict__ outp) {
    constexpr int LPE = C / 4;
    constexpr int EPC = 32 / LPE;
    const int n = (blockIdx.x * blockDim.x + threadIdx.x) >> 5;
    const int lane = threadIdx.x & 31;
    if (n >= NN) return;
    const int sub = lane / LPE;
    const int li = lane % LPE;

    const int beg = n << 6;
    const int end = beg + count[n];
    const float adv = __ldg(&ad[n]);

    float4 acc = make_float4(0.f, 0.f, 0.f, 0.f);
    float den = 0.0f;

    for (int base = beg; base < end; base += 32) {
        const int e = base + lane;
        int s = 0;
        float ex = 0.0f;
        if (e < end) { s = esrc[e]; ex = __expf(leaky(__ldg(&as[s]) + adv)); }
        den += ex;
        const int cnt = min(32, end - base);
        for (int j = 0; j < cnt; j += EPC) {
            int jj = j + sub;
            int sj = __shfl_sync(FULL, s, jj);
            float exj = __shfl_sync(FULL, ex, jj);
            if (exj > 0.0f) {
                uint2 pk = h2[sj * LPE + li];
                unpack_fma(pk, exj, acc);
            }
        }
    }

#pragma unroll
    for (int off = 16; off > 0; off >>= 1)
        den += __shfl_xor_sync(FULL, den, off);
#pragma unroll
    for (int off = LPE; off < 32; off <<= 1) {
        acc.x += __shfl_xor_sync(FULL, acc.x, off);
        acc.y += __shfl_xor_sync(FULL, acc.y, off);
        acc.z += __shfl_xor_sync(FULL, acc.z, off);
        acc.w += __shfl_xor_sync(FULL, acc.w, off);
    }

    if (sub == 0) {
        float inv = 1.0f / (den + 1e-16f);
        float4 bb = __ldg(&b4[li]);
        float4 o;
        o.x = acc.x * inv + bb.x;
        o.y = acc.y * inv + bb.y;
        o.z = acc.z * inv + bb.z;
        o.w = acc.w * inv + bb.w;
        if (ACT == 1) {
            o.x = 1.0f / (1.0f + __expf(-o.x));
            o.y = 1.0f / (1.0f + __expf(-o.y));
            o.z = 1.0f / (1.0f + __expf(-o.z));
            o.w = 1.0f / (1.0f + __expf(-o.w));
        } else {
            o.x = fmaxf(o.x, 0.f); o.y = fmaxf(o.y, 0.f);
            o.z = fmaxf(o.z, 0.f); o.w = fmaxf(o.w, 0.f);
        }
        if (OUTH)
            ((uint2*)outp)[n * LPE + li] = pack_h4(o);
        else
            ((float4*)outp)[n * LPE + li] = o;
    }
}

extern "C" void kernel_launch(void* const* d_in, const int* in_sizes, int n_in,
                              void* d_out, int out_size) {
    const int*   node_ids = (const int*)d_in[0];
    const float* feats    = (const float*)d_in[1];
    const int*   eidx     = (const int*)d_in[2];
    const float* emb      = (const float*)d_in[4];
    const float* W1 = (const float*)d_in[5];
    const float* a1s = (const float*)d_in[6];
    const float* a1d = (const float*)d_in[7];
    const float* b1 = (const float*)d_in[8];
    const float* W2 = (const float*)d_in[9];
    const float* a2s = (const float*)d_in[10];
    const float* a2d = (const float*)d_in[11];
    const float* b2 = (const float*)d_in[12];
    const float* W3 = (const float*)d_in[13];
    const float* a3s = (const float*)d_in[14];
    const float* a3d = (const float*)d_in[15];
    const float* b3 = (const float*)d_in[16];
    const float* W4 = (const float*)d_in[17];
    const float* a4s = (const float*)d_in[18];
    const float* a4d = (const float*)d_in[19];
    const float* b4 = (const float*)d_in[20];
    float* out = (float*)d_out;

    const int E = in_sizes[2] / 2;
    const int Etot = E + NN;
    const int* src = eidx;
    const int* dst = eidx + E;

    float4 *as4, *ad4;
    uint2 *h2, *xB2, *xC2;
    int *count, *esrc;
    cudaGetSymbolAddress((void**)&h2, g_h2);
    cudaGetSymbolAddress((void**)&xB2, g_xB2);
    cudaGetSymbolAddress((void**)&xC2, g_xC2);
    cudaGetSymbolAddress((void**)&as4, g_as4);
    cudaGetSymbolAddress((void**)&ad4, g_ad4);
    cudaGetSymbolAddress((void**)&count, g_count);
    cudaGetSymbolAddress((void**)&esrc, g_esrc);
    float* as = (float*)as4;
    float* ad = (float*)ad4;

    const int T = (Etot + 7) / 8;
    const int eb = (T + 255) / 256;
    const int nwb = (NN * 32 + 255) / 256;

    // Side stream: slot-CSR, overlapped with layer-1 GEMM.
    cudaStream_t s2;
    cudaStreamCreateWithFlags(&s2, cudaStreamNonBlocking);
    cudaEvent_t evA, evB;
    cudaEventCreateWithFlags(&evA, cudaEventDisableTiming);
    cudaEventCreateWithFlags(&evB, cudaEventDisableTiming);

    cudaEventRecord(evA, 0);
    cudaStreamWaitEvent(s2, evA, 0);

    cudaMemsetAsync(count, 0, NN * sizeof(int), s2);
    k_scatter<<<eb, 256, 0, s2>>>(src, dst, E, Etot, T, count, esrc);
    cudaEventRecord(evB, s2);

    // ---- Layer 1: 23 -> 4x32 (overlaps CSR build) ----
    k_mm1<<<(NN + 63) / 64, 256>>>(node_ids, feats, emb, (const float4*)W1,
                                   (const float4*)a1s, (const float4*)a1d,
                                   h2, as, ad);
    cudaStreamWaitEvent(0, evB, 0);
    k_agg4<<<nwb, 256>>>(count, esrc, as4, ad4, h2, (const float4*)b1, xB2);

    // ---- Layer 2: 128 -> 1x32 (NB=512, NR=2, NT=128, KT=64) ----
    k_mmt<128, 1, 32, 2, 512, 64><<<(NN + 127) / 128, 512>>>(xB2,
        (const float4*)W2, (const float4*)a2s, (const float4*)a2d, h2, as, ad);
    k_agg1<32, 0, 1><<<nwb, 256>>>(count, esrc, as, ad, h2, (const float4*)b2, xC2);

    // ---- Layer 3: 32 -> 4x32 (NB=512, NR=4, NT=64, KT=32) ----
    k_mmt<32, 4, 32, 4, 512, 32><<<(NN + 63) / 64, 512>>>(xC2,
        (const float4*)W3, (const float4*)a3s, (const float4*)a3d, h2, as, ad);
    k_agg4<<<nwb, 256>>>(count, esrc, as4, ad4, h2, (const float4*)b3, xB2);

    // ---- Layer 4: 128 -> 1x16, sigmoid (NB=512, NR=1, NT=128, KT=64) ----
    k_mmt<128, 1, 16, 1, 512, 64><<<(NN + 127) / 128, 512>>>(xB2,
        (const float4*)W4, (const float4*)a4s, (const float4*)a4d, h2, as, ad);
    k_agg1<16, 1, 0><<<nwb, 256>>>(count, esrc, as, ad, h2, (const float4*)b4, out);
}

// round 13
// speedup vs baseline: 1.0189x; 1.0189x over previous
#include <cuda_runtime.h>
#include <cuda_fp16.h>
#include <cuda_bf16.h>
#include <math_constants.h>

#define NN 50000
#define EE 800000
#define ETOT (EE + NN)
#define EMB_DIM 8
#define FEAT_DIM 15
#define GAT_IN 23
#define CAP 64
#define FULL 0xffffffffu

// Scratch (__device__ globals) — feature tensors fp16-packed (uint2 = 4 halves)
__device__ uint2  g_h2[NN * 32];      // h (post-GEMM messages)
__device__ uint2  g_xB2[NN * 32];     // activations ping
__device__ uint2  g_xC2[NN * 32];     // activations pong
__device__ float4 g_as4[NN];          // alpha_src (up to 4 heads, fp32)
__device__ float4 g_ad4[NN];          // alpha_dst
__device__ int   g_count[NN];
__device__ int   g_esrc[NN * CAP];

__device__ __forceinline__ float leaky(float v) {
    return v > 0.0f ? v : 0.2f * v;
}

__device__ __forceinline__ uint2 pack_h4(float4 a) {
    __half2 lo = __floats2half2_rn(a.x, a.y);
    __half2 hi = __floats2half2_rn(a.z, a.w);
    return make_uint2(*(unsigned*)&lo, *(unsigned*)&hi);
}

__device__ __forceinline__ float4 unpack_h4(uint2 pk) {
    __half2 lo = *(__half2*)&pk.x;
    __half2 hi = *(__half2*)&pk.y;
    float2 f0 = __half22float2(lo);
    float2 f1 = __half22float2(hi);
    return make_float4(f0.x, f0.y, f1.x, f1.y);
}

__device__ __forceinline__ void unpack_fma(uint2 pk, float exj, float4& acc) {
    float4 f = unpack_h4(pk);
    acc.x = fmaf(exj, f.x, acc.x);
    acc.y = fmaf(exj, f.y, acc.y);
    acc.z = fmaf(exj, f.z, acc.z);
    acc.w = fmaf(exj, f.w, acc.w);
}

// ---- packed f32x2 helpers (SASS FFMA2; PTX-only on sm_103a) ----
__device__ __forceinline__ unsigned long long pk2(float a, float b) {
    unsigned long long r;
    asm("mov.b64 %0, {%1, %2};" : "=l"(r) : "f"(a), "f"(b));
    return r;
}
__device__ __forceinline__ void ffma2(unsigned long long& d,
                                      unsigned long long a,
                                      unsigned long long b) {
    asm("fma.rn.f32x2 %0, %1, %2, %0;" : "+l"(d) : "l"(a), "l"(b));
}
__device__ __forceinline__ float2 unpk2(unsigned long long v) {
    float2 r;
    asm("mov.b64 {%0, %1}, %2;" : "=f"(r.x), "=f"(r.y) : "l"(v));
    return r;
}

// ===========================================================================
// One-pass slot-CSR (ILP 8 to overlap ATOMG latency chains).
// ===========================================================================
__global__ void k_scatter(const int* __restrict__ src,
                          const int* __restrict__ dst, int E, int Etot, int T,
                          int* __restrict__ count, int* __restrict__ esrc) {
    const int g = blockIdx.x * blockDim.x + threadIdx.x;
#pragma unroll
    for (int k = 0; k < 8; k++) {
        int e = g + k * T;
        if (e < Etot) {
            int s, d;
            if (e < E) { s = __ldg(&src[e]); d = __ldg(&dst[e]); }
            else       { s = d = e - E; }
            int pos = atomicAdd(&count[d], 1);
            esrc[(d << 6) + pos] = s;
        }
    }
}

// ===========================================================================
// Layer-1 GEMM: 256 thr, NT=64, NR=8. x stored duplicated (float2) in smem
// so the FFMA2 multiplier is a single broadcast LDS.64.
// ===========================================================================
__global__ void k_mm1(const int* __restrict__ node_ids,
                      const float* __restrict__ feats,
                      const float* __restrict__ emb,
                      const float4* __restrict__ W4,
                      const float4* __restrict__ asw4,
                      const float4* __restrict__ adw4,
                      uint2* __restrict__ h2,
                      float* __restrict__ as_o, float* __restrict__ ad_o) {
    constexpr int QC = 32, TY = 8, NR = 8, NT = 64;
    __shared__ float4 Ws4[GAT_IN * QC];
    __shared__ float2 xsd[NT * 33];   // duplicated (x,x) per entry

    const int tid = threadIdx.x;
    const int tx = tid & 31;
    const int ty = tid >> 5;
    const int blockBase = blockIdx.x * NT;

    for (int i = tid; i < GAT_IN * QC; i += 256)
        Ws4[i] = W4[i];

    for (int i = tid; i < NT * 32; i += 256) {
        int l = i >> 5;
        int k = i & 31;
        int n = blockBase + l;
        float v = 0.0f;
        if (n < NN && k < GAT_IN) {
            if (k < EMB_DIM) v = emb[__ldg(&node_ids[n]) * EMB_DIM + k];
            else             v = feats[n * FEAT_DIM + (k - EMB_DIM)];
        }
        xsd[l * 33 + k] = make_float2(v, v);
    }
    __syncthreads();

    unsigned long long accL[NR], accH[NR];
#pragma unroll
    for (int r = 0; r < NR; r++) { accL[r] = pk2(0.f, 0.f); accH[r] = pk2(0.f, 0.f); }

#pragma unroll
    for (int k = 0; k < GAT_IN; k++) {
        ulonglong2 w2 = *reinterpret_cast<const ulonglong2*>(&Ws4[k * QC + tx]);
#pragma unroll
        for (int r = 0; r < NR; r++) {
            unsigned long long xx = *reinterpret_cast<const unsigned long long*>(
                &xsd[(ty + TY * r) * 33 + k]);
            ffma2(accL[r], xx, w2.x);
            ffma2(accH[r], xx, w2.y);
        }
    }

    const float4 aw = __ldg(&asw4[tx]);
    const float4 dw = __ldg(&adw4[tx]);
#pragma unroll
    for (int r = 0; r < NR; r++) {
        int n = blockBase + ty + TY * r;
        float2 lo = unpk2(accL[r]);
        float2 hi = unpk2(accH[r]);
        float4 acc = make_float4(lo.x, lo.y, hi.x, hi.y);
        float s = acc.x * aw.x + acc.y * aw.y + acc.z * aw.z + acc.w * aw.w;
        float d = acc.x * dw.x + acc.y * dw.y + acc.z * dw.z + acc.w * dw.w;
#pragma unroll
        for (int off = 4; off > 0; off >>= 1) {
            s += __shfl_down_sync(FULL, s, off, 8);
            d += __shfl_down_sync(FULL, d, off, 8);
        }
        if (n < NN) {
            h2[n * QC + tx] = pack_h4(acc);
            if ((tx & 7) == 0) {
                int head = tx >> 3;
                as_o[n * 4 + head] = s;
                ad_o[n * 4 + head] = d;
            }
        }
    }
}

// ===========================================================================
// Register-tiled GEMM (layers 2-4): NB threads, NR nodes x 4 chans each,
// FFMA2 inner loop; x stored DUPLICATED (float2) in smem -> LDS.64 multiplier.
// ===========================================================================
template <int FIN, int H, int C, int NR, int NB, int KT>
__global__ void __launch_bounds__(NB)
k_mmt(const uint2* __restrict__ x2,
      const float4* __restrict__ W4,
      const float4* __restrict__ asw4,
      const float4* __restrict__ adw4,
      uint2* __restrict__ h2,
      float* __restrict__ as_o, float* __restrict__ ad_o) {
    constexpr int HC = H * C;
    constexpr int QC = HC / 4;
    constexpr int TY = NB / QC;
    constexpr int NT = TY * NR;
    constexpr int K4 = KT / 4;
    constexpr int QF = FIN / 4;
    constexpr int GPH = C / 4;
    constexpr int XROW = KT + 1;      // float2 row stride (pad)

    __shared__ float4 Ws4[FIN * QC];
    __shared__ float2 xsd[NT * XROW];

    const int tid = threadIdx.x;
    const int tx = tid % QC;
    const int ty = tid / QC;
    const int blockBase = blockIdx.x * NT;

    for (int i = tid; i < FIN * QC; i += NB)
        Ws4[i] = W4[i];

    unsigned long long accL[NR], accH[NR];
#pragma unroll
    for (int r = 0; r < NR; r++) { accL[r] = pk2(0.f, 0.f); accH[r] = pk2(0.f, 0.f); }

    for (int kb = 0; kb < FIN; kb += KT) {
        __syncthreads();
        for (int i = tid; i < NT * K4; i += NB) {
            int l = i / K4;
            int c4 = i % K4;
            int n = blockBase + l;
            float4 v = (n < NN) ? unpack_h4(x2[n * QF + kb / 4 + c4])
                                : make_float4(0.f, 0.f, 0.f, 0.f);
            float2* row = &xsd[l * XROW + c4 * 4];
            row[0] = make_float2(v.x, v.x);
            row[1] = make_float2(v.y, v.y);
            row[2] = make_float2(v.z, v.z);
            row[3] = make_float2(v.w, v.w);
        }
        __syncthreads();
#pragma unroll
        for (int k4 = 0; k4 < K4; k4++) {
#pragma unroll
            for (int kk = 0; kk < 4; kk++) {
                const int k = k4 * 4 + kk;
                ulonglong2 w2 = *reinterpret_cast<const ulonglong2*>(
                    &Ws4[(kb + k) * QC + tx]);
#pragma unroll
                for (int r = 0; r < NR; r++) {
                    unsigned long long xx =
                        *reinterpret_cast<const unsigned long long*>(
                            &xsd[(ty + TY * r) * XROW + k]);
                    ffma2(accL[r], xx, w2.x);
                    ffma2(accH[r], xx, w2.y);
                }
            }
        }
    }

    const float4 aw = __ldg(&asw4[tx]);
    const float4 dw = __ldg(&adw4[tx]);
#pragma unroll
    for (int r = 0; r < NR; r++) {
        int n = blockBase + ty + TY * r;
        float2 lo = unpk2(accL[r]);
        float2 hi = unpk2(accH[r]);
        float4 acc = make_float4(lo.x, lo.y, hi.x, hi.y);
        float s = acc.x * aw.x + acc.y * aw.y + acc.z * aw.z + acc.w * aw.w;
        float d = acc.x * dw.x + acc.y * dw.y + acc.z * dw.z + acc.w * dw.w;
#pragma unroll
        for (int off = GPH / 2; off > 0; off >>= 1) {
            s += __shfl_down_sync(FULL, s, off, GPH);
            d += __shfl_down_sync(FULL, d, off, GPH);
        }
        if (n < NN) {
            h2[n * QC + tx] = pack_h4(acc);
            if ((tx % GPH) == 0) {
                int head = tx / GPH;
                as_o[n * H + head] = s;
                ad_o[n * H + head] = d;
            }
        }
    }
}

// ===========================================================================
// Aggregation H=4, C=32: warp per node, single pass, fp16 h gather + fp16 out.
// ===========================================================================
__global__ void k_agg4(const int* __restrict__ count,
                       const int* __restrict__ esrc,
                       const float4* __restrict__ as4,
                       const float4* __restrict__ ad4,
                       const uint2* __restrict__ h2,
                       const float4* __restrict__ b4,
                       uint2* __restrict__ out2) {
    __shared__ float4 sEx[8][32];
    __shared__ int sSj[8][32];
    const int n = (blockIdx.x * blockDim.x + threadIdx.x) >> 5;
    const int w = (threadIdx.x >> 5);
    const int lane = threadIdx.x & 31;
    if (n >= NN) return;
    const int hd = lane >> 3;

    const int beg = n << 6;
    const int end = beg + count[n];
    const float4 adn = __ldg(&ad4[n]);

    float4 acc = make_float4(0.f, 0.f, 0.f, 0.f);
    float4 dsum = make_float4(0.f, 0.f, 0.f, 0.f);

    for (int base = beg; base < end; base += 32) {
        const int e = base + lane;
        float4 ex = make_float4(0.f, 0.f, 0.f, 0.f);
        int s = 0;
        if (e < end) {
            s = esrc[e];
            float4 a = __ldg(&as4[s]);
            ex.x = __expf(leaky(a.x + adn.x));
            ex.y = __expf(leaky(a.y + adn.y));
            ex.z = __expf(leaky(a.z + adn.z));
            ex.w = __expf(leaky(a.w + adn.w));
        }
        dsum.x += ex.x; dsum.y += ex.y; dsum.z += ex.z; dsum.w += ex.w;
        __syncwarp();
        sEx[w][lane] = ex;
        sSj[w][lane] = s;
        __syncwarp();
        const int cnt = min(32, end - base);
#pragma unroll 2
        for (int j = 0; j < cnt; j++) {
            int sj = sSj[w][j];
            float exj = ((const float*)&sEx[w][j])[hd];
            uint2 pk = h2[sj * 32 + lane];
            unpack_fma(pk, exj, acc);
        }
    }

#pragma unroll
    for (int off = 16; off > 0; off >>= 1) {
        dsum.x += __shfl_xor_sync(FULL, dsum.x, off);
        dsum.y += __shfl_xor_sync(FULL, dsum.y, off);
        dsum.z += __shfl_xor_sync(FULL, dsum.z, off);
        dsum.w += __shfl_xor_sync(FULL, dsum.w, off);
    }
    float den = (hd == 0) ? dsum.x : (hd == 1) ? dsum.y : (hd == 2) ? dsum.z : dsum.w;
    float inv = 1.0f / (den + 1e-16f);
    float4 bb = __ldg(&b4[lane]);
    float4 o;
    o.x = fmaxf(acc.x * inv + bb.x, 0.f);
    o.y = fmaxf(acc.y * inv + bb.y, 0.f);
    o.z = fmaxf(acc.z * inv + bb.z, 0.f);
    o.w = fmaxf(acc.w * inv + bb.w, 0.f);
    out2[n * 32 + lane] = pack_h4(o);
}

// ===========================================================================
// Aggregation H=1: warp per node; OUTH=1 -> fp16 out, else fp32 out.
// ===========================================================================
template <int C, int ACT, int OUTH>
__global__ void k_agg1(const int* __restrict__ count,
                       const int* __restrict__ esrc,
                       const float* __restrict__ as,
                       const float* __restrict__ ad,
                       const uint2* __restrict__ h2,
                       const float4* __restrict__ b4,
                       void* __restrict__ outp) {
    constexpr int LPE = C / 4;
    constexpr int EPC = 32 / LPE;
    const int n = (blockIdx.x * blockDim.x + threadIdx.x) >> 5;
    const int lane = threadIdx.x & 31;
    if (n >= NN) return;
    const int sub = lane / LPE;
    const int li = lane % LPE;

    const int beg = n << 6;
    const int end = beg + count[n];
    const float adv = __ldg(&ad[n]);

    float4 acc = make_float4(0.f, 0.f, 0.f, 0.f);
    float den = 0.0f;

    for (int base = beg; base < end; base += 32) {
        const int e = base + lane;
        int s = 0;
        float ex = 0.0f;
        if (e < end) { s = esrc[e]; ex = __expf(leaky(__ldg(&as[s]) + adv)); }
        den += ex;
        const int cnt = min(32, end - base);
        for (int j = 0; j < cnt; j += EPC) {
            int jj = j + sub;
            int sj = __shfl_sync(FULL, s, jj);
            float exj = __shfl_sync(FULL, ex, jj);
            if (exj > 0.0f) {
                uint2 pk = h2[sj * LPE + li];
                unpack_fma(pk, exj, acc);
            }
        }
    }

#pragma unroll
    for (int off = 16; off > 0; off >>= 1)
        den += __shfl_xor_sync(FULL, den, off);
#pragma unroll
    for (int off = LPE; off < 32; off <<= 1) {
        acc.x += __shfl_xor_sync(FULL, acc.x, off);
        acc.y += __shfl_xor_sync(FULL, acc.y, off);
        acc.z += __shfl_xor_sync(FULL, acc.z, off);
        acc.w += __shfl_xor_sync(FULL, acc.w, off);
    }

    if (sub == 0) {
        float inv = 1.0f / (den + 1e-16f);
        float4 bb = __ldg(&b4[li]);
        float4 o;
        o.x = acc.x * inv + bb.x;
        o.y = acc.y * inv + bb.y;
        o.z = acc.z * inv + bb.z;
        o.w = acc.w * inv + bb.w;
        if (ACT == 1) {
            o.x = 1.0f / (1.0f + __expf(-o.x));
            o.y = 1.0f / (1.0f + __expf(-o.y));
            o.z = 1.0f / (1.0f + __expf(-o.z));
            o.w = 1.0f / (1.0f + __expf(-o.w));
        } else {
            o.x = fmaxf(o.x, 0.f); o.y = fmaxf(o.y, 0.f);
            o.z = fmaxf(o.z, 0.f); o.w = fmaxf(o.w, 0.f);
        }
        if (OUTH)
            ((uint2*)outp)[n * LPE + li] = pack_h4(o);
        else
            ((float4*)outp)[n * LPE + li] = o;
    }
}

extern "C" void kernel_launch(void* const* d_in, const int* in_sizes, int n_in,
                              void* d_out, int out_size) {
    const int*   node_ids = (const int*)d_in[0];
    const float* feats    = (const float*)d_in[1];
    const int*   eidx     = (const int*)d_in[2];
    const float* emb      = (const float*)d_in[4];
    const float* W1 = (const float*)d_in[5];
    const float* a1s = (const float*)d_in[6];
    const float* a1d = (const float*)d_in[7];
    const float* b1 = (const float*)d_in[8];
    const float* W2 = (const float*)d_in[9];
    const float* a2s = (const float*)d_in[10];
    const float* a2d = (const float*)d_in[11];
    const float* b2 = (const float*)d_in[12];
    const float* W3 = (const float*)d_in[13];
    const float* a3s = (const float*)d_in[14];
    const float* a3d = (const float*)d_in[15];
    const float* b3 = (const float*)d_in[16];
    const float* W4 = (const float*)d_in[17];
    const float* a4s = (const float*)d_in[18];
    const float* a4d = (const float*)d_in[19];
    const float* b4 = (const float*)d_in[20];
    float* out = (float*)d_out;

    const int E = in_sizes[2] / 2;
    const int Etot = E + NN;
    const int* src = eidx;
    const int* dst = eidx + E;

    float4 *as4, *ad4;
    uint2 *h2, *xB2, *xC2;
    int *count, *esrc;
    cudaGetSymbolAddress((void**)&h2, g_h2);
    cudaGetSymbolAddress((void**)&xB2, g_xB2);
    cudaGetSymbolAddress((void**)&xC2, g_xC2);
    cudaGetSymbolAddress((void**)&as4, g_as4);
    cudaGetSymbolAddress((void**)&ad4, g_ad4);
    cudaGetSymbolAddress((void**)&count, g_count);
    cudaGetSymbolAddress((void**)&esrc, g_esrc);
    float* as = (float*)as4;
    float* ad = (float*)ad4;

    const int T = (Etot + 7) / 8;
    const int eb = (T + 255) / 256;
    const int nwb = (NN * 32 + 255) / 256;

    // Side stream: slot-CSR, overlapped with layer-1 GEMM.
    cudaStream_t s2;
    cudaStreamCreateWithFlags(&s2, cudaStreamNonBlocking);
    cudaEvent_t evA, evB;
    cudaEventCreateWithFlags(&evA, cudaEventDisableTiming);
    cudaEventCreateWithFlags(&evB, cudaEventDisableTiming);

    cudaEventRecord(evA, 0);
    cudaStreamWaitEvent(s2, evA, 0);

    cudaMemsetAsync(count, 0, NN * sizeof(int), s2);
    k_scatter<<<eb, 256, 0, s2>>>(src, dst, E, Etot, T, count, esrc);
    cudaEventRecord(evB, s2);

    // ---- Layer 1: 23 -> 4x32 (overlaps CSR build) ----
    k_mm1<<<(NN + 63) / 64, 256>>>(node_ids, feats, emb, (const float4*)W1,
                                   (const float4*)a1s, (const float4*)a1d,
                                   h2, as, ad);
    cudaStreamWaitEvent(0, evB, 0);
    k_agg4<<<nwb, 256>>>(count, esrc, as4, ad4, h2, (const float4*)b1, xB2);

    // ---- Layer 2: 128 -> 1x32 (NB=256, NR=4, NT=128, KT=32) ----
    k_mmt<128, 1, 32, 4, 256, 32><<<(NN + 127) / 128, 256>>>(xB2,
        (const float4*)W2, (const float4*)a2s, (const float4*)a2d, h2, as, ad);
    k_agg1<32, 0, 1><<<nwb, 256>>>(count, esrc, as, ad, h2, (const float4*)b2, xC2);

    // ---- Layer 3: 32 -> 4x32 (NB=256, NR=8, NT=64, KT=32) ----
    k_mmt<32, 4, 32, 8, 256, 32><<<(NN + 63) / 64, 256>>>(xC2,
        (const float4*)W3, (const float4*)a3s, (const float4*)a3d, h2, as, ad);
    k_agg4<<<nwb, 256>>>(count, esrc, as4, ad4, h2, (const float4*)b3, xB2);

    // ---- Layer 4: 128 -> 1x16, sigmoid (NB=256, NR=2, NT=128, KT=32) ----
    k_mmt<128, 1, 16, 2, 256, 32><<<(NN + 127) / 128, 256>>>(xB2,
        (const float4*)W4, (const float4*)a4s, (const float4*)a4d, h2, as, ad);
    k_agg1<16, 1, 0><<<nwb, 256>>>(count, esrc, as, ad, h2, (const float4*)b4, out);
}

// round 14
// speedup vs baseline: 1.0770x; 1.0570x over previous
#include <cuda_runtime.h>
#include <cuda_fp16.h>
#include <cuda_bf16.h>
#include <math_constants.h>

#define NN 50000
#define EE 800000
#define ETOT (EE + NN)
#define EMB_DIM 8
#define FEAT_DIM 15
#define GAT_IN 23
#define CAP 64
#define FULL 0xffffffffu

// Scratch (__device__ globals) — feature tensors fp16-packed (uint2 = 4 halves)
__device__ uint2  g_h2[NN * 32];      // h (post-GEMM messages)
__device__ uint2  g_xB2[NN * 32];     // activations ping
__device__ uint2  g_xC2[NN * 32];     // activations pong
__device__ float4 g_as4[NN];          // alpha_src (up to 4 heads, fp32)
__device__ float4 g_ad4[NN];          // alpha_dst
__device__ int   g_count[NN];
__device__ int   g_esrc[NN * CAP];

__device__ __forceinline__ float leaky(float v) {
    return v > 0.0f ? v : 0.2f * v;
}

__device__ __forceinline__ uint2 pack_h4(float4 a) {
    __half2 lo = __floats2half2_rn(a.x, a.y);
    __half2 hi = __floats2half2_rn(a.z, a.w);
    return make_uint2(*(unsigned*)&lo, *(unsigned*)&hi);
}

__device__ __forceinline__ float4 unpack_h4(uint2 pk) {
    __half2 lo = *(__half2*)&pk.x;
    __half2 hi = *(__half2*)&pk.y;
    float2 f0 = __half22float2(lo);
    float2 f1 = __half22float2(hi);
    return make_float4(f0.x, f0.y, f1.x, f1.y);
}

__device__ __forceinline__ void unpack_fma(uint2 pk, float exj, float4& acc) {
    float4 f = unpack_h4(pk);
    acc.x = fmaf(exj, f.x, acc.x);
    acc.y = fmaf(exj, f.y, acc.y);
    acc.z = fmaf(exj, f.z, acc.z);
    acc.w = fmaf(exj, f.w, acc.w);
}

// ---- packed f32x2 helpers (SASS FFMA2; PTX-only on sm_103a) ----
__device__ __forceinline__ unsigned long long pk2(float a, float b) {
    unsigned long long r;
    asm("mov.b64 %0, {%1, %2};" : "=l"(r) : "f"(a), "f"(b));
    return r;
}
__device__ __forceinline__ void ffma2(unsigned long long& d,
                                      unsigned long long a,
                                      unsigned long long b) {
    asm("fma.rn.f32x2 %0, %1, %2, %0;" : "+l"(d) : "l"(a), "l"(b));
}
__device__ __forceinline__ float2 unpk2(unsigned long long v) {
    float2 r;
    asm("mov.b64 {%0, %1}, %2;" : "=f"(r.x), "=f"(r.y) : "l"(v));
    return r;
}

// ===========================================================================
// One-pass slot-CSR (ILP 8 to overlap ATOMG latency chains).
// ===========================================================================
__global__ void k_scatter(const int* __restrict__ src,
                          const int* __restrict__ dst, int E, int Etot, int T,
                          int* __restrict__ count, int* __restrict__ esrc) {
    const int g = blockIdx.x * blockDim.x + threadIdx.x;
#pragma unroll
    for (int k = 0; k < 8; k++) {
        int e = g + k * T;
        if (e < Etot) {
            int s, d;
            if (e < E) { s = __ldg(&src[e]); d = __ldg(&dst[e]); }
            else       { s = d = e - E; }
            int pos = atomicAdd(&count[d], 1);
            esrc[(d << 6) + pos] = s;
        }
    }
}

// ===========================================================================
// Layer-1 GEMM: 256 thr, NT=64 nodes/block, NR=8, FFMA2 inner loop.
// ===========================================================================
__global__ void k_mm1(const int* __restrict__ node_ids,
                      const float* __restrict__ feats,
                      const float* __restrict__ emb,
                      const float4* __restrict__ W4,
                      const float4* __restrict__ asw4,
                      const float4* __restrict__ adw4,
                      uint2* __restrict__ h2,
                      float* __restrict__ as_o, float* __restrict__ ad_o) {
    constexpr int QC = 32, TY = 8, NR = 8, NT = 64;
    __shared__ float4 Ws4[GAT_IN * QC];
    __shared__ float xs[NT * 33];

    const int tid = threadIdx.x;
    const int tx = tid & 31;
    const int ty = tid >> 5;
    const int blockBase = blockIdx.x * NT;

    for (int i = tid; i < GAT_IN * QC; i += 256)
        Ws4[i] = W4[i];

    for (int i = tid; i < NT * 32; i += 256) {
        int l = i >> 5;
        int k = i & 31;
        int n = blockBase + l;
        float v = 0.0f;
        if (n < NN && k < GAT_IN) {
            if (k < EMB_DIM) v = emb[__ldg(&node_ids[n]) * EMB_DIM + k];
            else             v = feats[n * FEAT_DIM + (k - EMB_DIM)];
        }
        xs[l * 33 + k] = v;
    }
    __syncthreads();

    unsigned long long accL[NR], accH[NR];
#pragma unroll
    for (int r = 0; r < NR; r++) { accL[r] = pk2(0.f, 0.f); accH[r] = pk2(0.f, 0.f); }

#pragma unroll
    for (int k = 0; k < GAT_IN; k++) {
        ulonglong2 w2 = *reinterpret_cast<const ulonglong2*>(&Ws4[k * QC + tx]);
#pragma unroll
        for (int r = 0; r < NR; r++) {
            float xv = xs[(ty + TY * r) * 33 + k];
            unsigned long long xx = pk2(xv, xv);
            ffma2(accL[r], xx, w2.x);
            ffma2(accH[r], xx, w2.y);
        }
    }

    const float4 aw = __ldg(&asw4[tx]);
    const float4 dw = __ldg(&adw4[tx]);
#pragma unroll
    for (int r = 0; r < NR; r++) {
        int n = blockBase + ty + TY * r;
        float2 lo = unpk2(accL[r]);
        float2 hi = unpk2(accH[r]);
        float4 acc = make_float4(lo.x, lo.y, hi.x, hi.y);
        float s = acc.x * aw.x + acc.y * aw.y + acc.z * aw.z + acc.w * aw.w;
        float d = acc.x * dw.x + acc.y * dw.y + acc.z * dw.z + acc.w * dw.w;
#pragma unroll
        for (int off = 4; off > 0; off >>= 1) {
            s += __shfl_down_sync(FULL, s, off, 8);
            d += __shfl_down_sync(FULL, d, off, 8);
        }
        if (n < NN) {
            h2[n * QC + tx] = pack_h4(acc);
            if ((tx & 7) == 0) {
                int head = tx >> 3;
                as_o[n * 4 + head] = s;
                ad_o[n * 4 + head] = d;
            }
        }
    }
}

// ===========================================================================
// Register-tiled GEMM (layers 2-4): NB threads, NR nodes x 4 chans each,
// FFMA2 inner loop; W quads read as ulonglong2 (same LDS.128).
// ===========================================================================
template <int FIN, int H, int C, int NR, int NB, int KT>
__global__ void __launch_bounds__(NB)
k_mmt(const uint2* __restrict__ x2,
      const float4* __restrict__ W4,
      const float4* __restrict__ asw4,
      const float4* __restrict__ adw4,
      uint2* __restrict__ h2,
      float* __restrict__ as_o, float* __restrict__ ad_o) {
    constexpr int HC = H * C;
    constexpr int QC = HC / 4;
    constexpr int TY = NB / QC;
    constexpr int NT = TY * NR;
    constexpr int K4 = KT / 4;
    constexpr int QF = FIN / 4;
    constexpr int GPH = C / 4;

    __shared__ float4 Ws4[FIN * QC];
    __shared__ float4 xs4[NT][K4 + 1];

    const int tid = threadIdx.x;
    const int tx = tid % QC;
    const int ty = tid / QC;
    const int blockBase = blockIdx.x * NT;

    for (int i = tid; i < FIN * QC; i += NB)
        Ws4[i] = W4[i];

    unsigned long long accL[NR], accH[NR];
#pragma unroll
    for (int r = 0; r < NR; r++) { accL[r] = pk2(0.f, 0.f); accH[r] = pk2(0.f, 0.f); }

    for (int kb = 0; kb < FIN; kb += KT) {
        __syncthreads();
        for (int i = tid; i < NT * K4; i += NB) {
            int l = i / K4;
            int c4 = i % K4;
            int n = blockBase + l;
            xs4[l][c4] = (n < NN) ? unpack_h4(x2[n * QF + kb / 4 + c4])
                                  : make_float4(0.f, 0.f, 0.f, 0.f);
        }
        __syncthreads();
#pragma unroll
        for (int k4 = 0; k4 < K4; k4++) {
            float4 xv[NR];
#pragma unroll
            for (int r = 0; r < NR; r++)
                xv[r] = xs4[ty + TY * r][k4];
#pragma unroll
            for (int kk = 0; kk < 4; kk++) {
                ulonglong2 w2 = *reinterpret_cast<const ulonglong2*>(
                    &Ws4[(kb + k4 * 4 + kk) * QC + tx]);
#pragma unroll
                for (int r = 0; r < NR; r++) {
                    float xvk = (kk == 0) ? xv[r].x : (kk == 1) ? xv[r].y
                              : (kk == 2) ? xv[r].z : xv[r].w;
                    unsigned long long xx = pk2(xvk, xvk);
                    ffma2(accL[r], xx, w2.x);
                    ffma2(accH[r], xx, w2.y);
                }
            }
        }
    }

    const float4 aw = __ldg(&asw4[tx]);
    const float4 dw = __ldg(&adw4[tx]);
#pragma unroll
    for (int r = 0; r < NR; r++) {
        int n = blockBase + ty + TY * r;
        float2 lo = unpk2(accL[r]);
        float2 hi = unpk2(accH[r]);
        float4 acc = make_float4(lo.x, lo.y, hi.x, hi.y);
        float s = acc.x * aw.x + acc.y * aw.y + acc.z * aw.z + acc.w * aw.w;
        float d = acc.x * dw.x + acc.y * dw.y + acc.z * dw.z + acc.w * dw.w;
#pragma unroll
        for (int off = GPH / 2; off > 0; off >>= 1) {
            s += __shfl_down_sync(FULL, s, off, GPH);
            d += __shfl_down_sync(FULL, d, off, GPH);
        }
        if (n < NN) {
            h2[n * QC + tx] = pack_h4(acc);
            if ((tx % GPH) == 0) {
                int head = tx / GPH;
                as_o[n * H + head] = s;
                ad_o[n * H + head] = d;
            }
        }
    }
}

// ===========================================================================
// Aggregation H=4, C=32: warp per node, single pass, fp16 h gather + fp16 out.
// ===========================================================================
__global__ void k_agg4(const int* __restrict__ count,
                       const int* __restrict__ esrc,
                       const float4* __restrict__ as4,
                       const float4* __restrict__ ad4,
                       const uint2* __restrict__ h2,
                       const float4* __restrict__ b4,
                       uint2* __restrict__ out2) {
    __shared__ float4 sEx[8][32];
    __shared__ int sSj[8][32];
    const int n = (blockIdx.x * blockDim.x + threadIdx.x) >> 5;
    const int w = (threadIdx.x >> 5);
    const int lane = threadIdx.x & 31;
    if (n >= NN) return;
    const int hd = lane >> 3;

    const int beg = n << 6;
    const int end = beg + count[n];
    const float4 adn = __ldg(&ad4[n]);

    float4 acc = make_float4(0.f, 0.f, 0.f, 0.f);
    float4 dsum = make_float4(0.f, 0.f, 0.f, 0.f);

    for (int base = beg; base < end; base += 32) {
        const int e = base + lane;
        float4 ex = make_float4(0.f, 0.f, 0.f, 0.f);
        int s = 0;
        if (e < end) {
            s = esrc[e];
            float4 a = __ldg(&as4[s]);
            ex.x = __expf(leaky(a.x + adn.x));
            ex.y = __expf(leaky(a.y + adn.y));
            ex.z = __expf(leaky(a.z + adn.z));
            ex.w = __expf(leaky(a.w + adn.w));
        }
        dsum.x += ex.x; dsum.y += ex.y; dsum.z += ex.z; dsum.w += ex.w;
        __syncwarp();
        sEx[w][lane] = ex;
        sSj[w][lane] = s;
        __syncwarp();
        const int cnt = min(32, end - base);
#pragma unroll 2
        for (int j = 0; j < cnt; j++) {
            int sj = sSj[w][j];
            float exj = ((const float*)&sEx[w][j])[hd];
            uint2 pk = h2[sj * 32 + lane];
            unpack_fma(pk, exj, acc);
        }
    }

#pragma unroll
    for (int off = 16; off > 0; off >>= 1) {
        dsum.x += __shfl_xor_sync(FULL, dsum.x, off);
        dsum.y += __shfl_xor_sync(FULL, dsum.y, off);
        dsum.z += __shfl_xor_sync(FULL, dsum.z, off);
        dsum.w += __shfl_xor_sync(FULL, dsum.w, off);
    }
    float den = (hd == 0) ? dsum.x : (hd == 1) ? dsum.y : (hd == 2) ? dsum.z : dsum.w;
    float inv = 1.0f / (den + 1e-16f);
    float4 bb = __ldg(&b4[lane]);
    float4 o;
    o.x = fmaxf(acc.x * inv + bb.x, 0.f);
    o.y = fmaxf(acc.y * inv + bb.y, 0.f);
    o.z = fmaxf(acc.z * inv + bb.z, 0.f);
    o.w = fmaxf(acc.w * inv + bb.w, 0.f);
    out2[n * 32 + lane] = pack_h4(o);
}

// ===========================================================================
// Aggregation H=1: warp per node; OUTH=1 -> fp16 out, else fp32 out.
// ===========================================================================
template <int C, int ACT, int OUTH>
__global__ void k_agg1(const int* __restrict__ count,
                       const int* __restrict__ esrc,
                       const float* __restrict__ as,
                       const float* __restrict__ ad,
                       const uint2* __restrict__ h2,
                       const float4* __restrict__ b4,
                       void* __restrict__ outp) {
    constexpr int LPE = C / 4;
    constexpr int EPC = 32 / LPE;
    const int n = (blockIdx.x * blockDim.x + threadIdx.x) >> 5;
    const int lane = threadIdx.x & 31;
    if (n >= NN) return;
    const int sub = lane / LPE;
    const int li = lane % LPE;

    const int beg = n << 6;
    const int end = beg + count[n];
    const float adv = __ldg(&ad[n]);

    float4 acc = make_float4(0.f, 0.f, 0.f, 0.f);
    float den = 0.0f;

    for (int base = beg; base < end; base += 32) {
        const int e = base + lane;
        int s = 0;
        float ex = 0.0f;
        if (e < end) { s = esrc[e]; ex = __expf(leaky(__ldg(&as[s]) + adv)); }
        den += ex;
        const int cnt = min(32, end - base);
        for (int j = 0; j < cnt; j += EPC) {
            int jj = j + sub;
            int sj = __shfl_sync(FULL, s, jj);
            float exj = __shfl_sync(FULL, ex, jj);
            if (exj > 0.0f) {
                uint2 pk = h2[sj * LPE + li];
                unpack_fma(pk, exj, acc);
            }
        }
    }

#pragma unroll
    for (int off = 16; off > 0; off >>= 1)
        den += __shfl_xor_sync(FULL, den, off);
#pragma unroll
    for (int off = LPE; off < 32; off <<= 1) {
        acc.x += __shfl_xor_sync(FULL, acc.x, off);
        acc.y += __shfl_xor_sync(FULL, acc.y, off);
        acc.z += __shfl_xor_sync(FULL, acc.z, off);
        acc.w += __shfl_xor_sync(FULL, acc.w, off);
    }

    if (sub == 0) {
        float inv = 1.0f / (den + 1e-16f);
        float4 bb = __ldg(&b4[li]);
        float4 o;
        o.x = acc.x * inv + bb.x;
        o.y = acc.y * inv + bb.y;
        o.z = acc.z * inv + bb.z;
        o.w = acc.w * inv + bb.w;
        if (ACT == 1) {
            o.x = 1.0f / (1.0f + __expf(-o.x));
            o.y = 1.0f / (1.0f + __expf(-o.y));
            o.z = 1.0f / (1.0f + __expf(-o.z));
            o.w = 1.0f / (1.0f + __expf(-o.w));
        } else {
            o.x = fmaxf(o.x, 0.f); o.y = fmaxf(o.y, 0.f);
            o.z = fmaxf(o.z, 0.f); o.w = fmaxf(o.w, 0.f);
        }
        if (OUTH)
            ((uint2*)outp)[n * LPE + li] = pack_h4(o);
        else
            ((float4*)outp)[n * LPE + li] = o;
    }
}

extern "C" void kernel_launch(void* const* d_in, const int* in_sizes, int n_in,
                              void* d_out, int out_size) {
    const int*   node_ids = (const int*)d_in[0];
    const float* feats    = (const float*)d_in[1];
    const int*   eidx     = (const int*)d_in[2];
    const float* emb      = (const float*)d_in[4];
    const float* W1 = (const float*)d_in[5];
    const float* a1s = (const float*)d_in[6];
    const float* a1d = (const float*)d_in[7];
    const float* b1 = (const float*)d_in[8];
    const float* W2 = (const float*)d_in[9];
    const float* a2s = (const float*)d_in[10];
    const float* a2d = (const float*)d_in[11];
    const float* b2 = (const float*)d_in[12];
    const float* W3 = (const float*)d_in[13];
    const float* a3s = (const float*)d_in[14];
    const float* a3d = (const float*)d_in[15];
    const float* b3 = (const float*)d_in[16];
    const float* W4 = (const float*)d_in[17];
    const float* a4s = (const float*)d_in[18];
    const float* a4d = (const float*)d_in[19];
    const float* b4 = (const float*)d_in[20];
    float* out = (float*)d_out;

    const int E = in_sizes[2] / 2;
    const int Etot = E + NN;
    const int* src = eidx;
    const int* dst = eidx + E;

    float4 *as4, *ad4;
    uint2 *h2, *xB2, *xC2;
    int *count, *esrc;
    cudaGetSymbolAddress((void**)&h2, g_h2);
    cudaGetSymbolAddress((void**)&xB2, g_xB2);
    cudaGetSymbolAddress((void**)&xC2, g_xC2);
    cudaGetSymbolAddress((void**)&as4, g_as4);
    cudaGetSymbolAddress((void**)&ad4, g_ad4);
    cudaGetSymbolAddress((void**)&count, g_count);
    cudaGetSymbolAddress((void**)&esrc, g_esrc);
    float* as = (float*)as4;
    float* ad = (float*)ad4;

    const int T = (Etot + 7) / 8;
    const int eb = (T + 255) / 256;
    const int nwb = (NN * 32 + 255) / 256;

    // Side stream: slot-CSR, overlapped with layer-1 GEMM.
    cudaStream_t s2;
    cudaStreamCreateWithFlags(&s2, cudaStreamNonBlocking);
    cudaEvent_t evA, evB;
    cudaEventCreateWithFlags(&evA, cudaEventDisableTiming);
    cudaEventCreateWithFlags(&evB, cudaEventDisableTiming);

    cudaEventRecord(evA, 0);
    cudaStreamWaitEvent(s2, evA, 0);

    cudaMemsetAsync(count, 0, NN * sizeof(int), s2);
    k_scatter<<<eb, 256, 0, s2>>>(src, dst, E, Etot, T, count, esrc);
    cudaEventRecord(evB, s2);

    // ---- Layer 1: 23 -> 4x32 (overlaps CSR build) ----
    k_mm1<<<(NN + 63) / 64, 256>>>(node_ids, feats, emb, (const float4*)W1,
                                   (const float4*)a1s, (const float4*)a1d,
                                   h2, as, ad);
    cudaStreamWaitEvent(0, evB, 0);
    k_agg4<<<nwb, 256>>>(count, esrc, as4, ad4, h2, (const float4*)b1, xB2);

    // ---- Layer 2: 128 -> 1x32 (NB=128, NR=4, NT=64 -> 782 blocks) ----
    k_mmt<128, 1, 32, 4, 128, 32><<<(NN + 63) / 64, 128>>>(xB2,
        (const float4*)W2, (const float4*)a2s, (const float4*)a2d, h2, as, ad);
    k_agg1<32, 0, 1><<<nwb, 256>>>(count, esrc, as, ad, h2, (const float4*)b2, xC2);

    // ---- Layer 3: 32 -> 4x32 (NB=256, NR=8, NT=64 -> 782 blocks) ----
    k_mmt<32, 4, 32, 8, 256, 32><<<(NN + 63) / 64, 256>>>(xC2,
        (const float4*)W3, (const float4*)a3s, (const float4*)a3d, h2, as, ad);
    k_agg4<<<nwb, 256>>>(count, esrc, as4, ad4, h2, (const float4*)b3, xB2);

    // ---- Layer 4: 128 -> 1x16, sigmoid (NB=128, NR=2, NT=64 -> 782 blocks) ----
    k_mmt<128, 1, 16, 2, 128, 32><<<(NN + 63) / 64, 128>>>(xB2,
        (const float4*)W4, (const float4*)a4s, (const float4*)a4d, h2, as, ad);
    k_agg1<16, 1, 0><<<nwb, 256>>>(count, esrc, as, ad, h2, (const float4*)b4, out);
}

// round 15
// speedup vs baseline: 1.1459x; 1.0639x over previous
#include <cuda_runtime.h>
#include <cuda_fp16.h>
#include <cuda_bf16.h>
#include <math_constants.h>

#define NN 50000
#define EE 800000
#define ETOT (EE + NN)
#define EMB_DIM 8
#define FEAT_DIM 15
#define GAT_IN 23
#define CAP 64
#define FULL 0xffffffffu

// Scratch (__device__ globals) — feature tensors fp16-packed (uint2 = 4 halves)
__device__ uint2  g_h2[NN * 32];      // h (post-GEMM messages)
__device__ uint2  g_xB2[NN * 32];     // activations ping
__device__ uint2  g_xC2[NN * 32];     // activations pong
__device__ float4 g_as4[NN];          // alpha_src (up to 4 heads, fp32)
__device__ float4 g_ad4[NN];          // alpha_dst
__device__ int   g_count[NN];
__device__ int   g_esrc[NN * CAP];

__device__ __forceinline__ float leaky(float v) {
    return v > 0.0f ? v : 0.2f * v;
}

__device__ __forceinline__ uint2 pack_h4(float4 a) {
    __half2 lo = __floats2half2_rn(a.x, a.y);
    __half2 hi = __floats2half2_rn(a.z, a.w);
    return make_uint2(*(unsigned*)&lo, *(unsigned*)&hi);
}

__device__ __forceinline__ float4 unpack_h4(uint2 pk) {
    __half2 lo = *(__half2*)&pk.x;
    __half2 hi = *(__half2*)&pk.y;
    float2 f0 = __half22float2(lo);
    float2 f1 = __half22float2(hi);
    return make_float4(f0.x, f0.y, f1.x, f1.y);
}

__device__ __forceinline__ void unpack_fma(uint2 pk, float exj, float4& acc) {
    float4 f = unpack_h4(pk);
    acc.x = fmaf(exj, f.x, acc.x);
    acc.y = fmaf(exj, f.y, acc.y);
    acc.z = fmaf(exj, f.z, acc.z);
    acc.w = fmaf(exj, f.w, acc.w);
}

// ---- packed f32x2 helpers (SASS FFMA2; PTX-only on sm_103a) ----
__device__ __forceinline__ unsigned long long pk2(float a, float b) {
    unsigned long long r;
    asm("mov.b64 %0, {%1, %2};" : "=l"(r) : "f"(a), "f"(b));
    return r;
}
__device__ __forceinline__ void ffma2(unsigned long long& d,
                                      unsigned long long a,
                                      unsigned long long b) {
    asm("fma.rn.f32x2 %0, %1, %2, %0;" : "+l"(d) : "l"(a), "l"(b));
}
__device__ __forceinline__ float2 unpk2(unsigned long long v) {
    float2 r;
    asm("mov.b64 {%0, %1}, %2;" : "=f"(r.x), "=f"(r.y) : "l"(v));
    return r;
}

// ===========================================================================
// One-pass slot-CSR (ILP 8 to overlap ATOMG latency chains).
// ===========================================================================
__global__ void k_scatter(const int* __restrict__ src,
                          const int* __restrict__ dst, int E, int Etot, int T,
                          int* __restrict__ count, int* __restrict__ esrc) {
    const int g = blockIdx.x * blockDim.x + threadIdx.x;
#pragma unroll
    for (int k = 0; k < 8; k++) {
        int e = g + k * T;
        if (e < Etot) {
            int s, d;
            if (e < E) { s = __ldg(&src[e]); d = __ldg(&dst[e]); }
            else       { s = d = e - E; }
            int pos = atomicAdd(&count[d], 1);
            esrc[(d << 6) + pos] = s;
        }
    }
}

// ===========================================================================
// Layer-1 GEMM: 256 thr, NT=64 nodes/block, NR=8, FFMA2 inner loop.
// (FIN=23 is odd-shaped; stays on CUDA cores, overlaps the CSR build.)
// ===========================================================================
__global__ void k_mm1(const int* __restrict__ node_ids,
                      const float* __restrict__ feats,
                      const float* __restrict__ emb,
                      const float4* __restrict__ W4,
                      const float4* __restrict__ asw4,
                      const float4* __restrict__ adw4,
                      uint2* __restrict__ h2,
                      float* __restrict__ as_o, float* __restrict__ ad_o) {
    constexpr int QC = 32, TY = 8, NR = 8, NT = 64;
    __shared__ float4 Ws4[GAT_IN * QC];
    __shared__ float xs[NT * 33];

    const int tid = threadIdx.x;
    const int tx = tid & 31;
    const int ty = tid >> 5;
    const int blockBase = blockIdx.x * NT;

    for (int i = tid; i < GAT_IN * QC; i += 256)
        Ws4[i] = W4[i];

    for (int i = tid; i < NT * 32; i += 256) {
        int l = i >> 5;
        int k = i & 31;
        int n = blockBase + l;
        float v = 0.0f;
        if (n < NN && k < GAT_IN) {
            if (k < EMB_DIM) v = emb[__ldg(&node_ids[n]) * EMB_DIM + k];
            else             v = feats[n * FEAT_DIM + (k - EMB_DIM)];
        }
        xs[l * 33 + k] = v;
    }
    __syncthreads();

    unsigned long long accL[NR], accH[NR];
#pragma unroll
    for (int r = 0; r < NR; r++) { accL[r] = pk2(0.f, 0.f); accH[r] = pk2(0.f, 0.f); }

#pragma unroll
    for (int k = 0; k < GAT_IN; k++) {
        ulonglong2 w2 = *reinterpret_cast<const ulonglong2*>(&Ws4[k * QC + tx]);
#pragma unroll
        for (int r = 0; r < NR; r++) {
            float xv = xs[(ty + TY * r) * 33 + k];
            unsigned long long xx = pk2(xv, xv);
            ffma2(accL[r], xx, w2.x);
            ffma2(accH[r], xx, w2.y);
        }
    }

    const float4 aw = __ldg(&asw4[tx]);
    const float4 dw = __ldg(&adw4[tx]);
#pragma unroll
    for (int r = 0; r < NR; r++) {
        int n = blockBase + ty + TY * r;
        float2 lo = unpk2(accL[r]);
        float2 hi = unpk2(accH[r]);
        float4 acc = make_float4(lo.x, lo.y, hi.x, hi.y);
        float s = acc.x * aw.x + acc.y * aw.y + acc.z * aw.z + acc.w * aw.w;
        float d = acc.x * dw.x + acc.y * dw.y + acc.z * dw.z + acc.w * dw.w;
#pragma unroll
        for (int off = 4; off > 0; off >>= 1) {
            s += __shfl_down_sync(FULL, s, off, 8);
            d += __shfl_down_sync(FULL, d, off, 8);
        }
        if (n < NN) {
            h2[n * QC + tx] = pack_h4(acc);
            if ((tx & 7) == 0) {
                int head = tx >> 3;
                as_o[n * 4 + head] = s;
                ad_o[n * 4 + head] = d;
            }
        }
    }
}

// ===========================================================================
// Tensor-core GEMM (layers 2-4): mma.sync m16n8k16 f16*f16->f32.
// 256 threads = 8 warps x 16-node M-tiles (NT=128 nodes/block).
// x fp16 staged in padded smem; W transposed to fp16 [HC][FIN] in smem.
// Epilogue: alpha dot products from C-fragments (width-4 shfl), fp16 h out.
// ===========================================================================
template <int FIN, int H, int C>
__global__ void __launch_bounds__(256)
k_hmma(const uint2* __restrict__ x2,
       const float* __restrict__ Wf,
       const float* __restrict__ asw,
       const float* __restrict__ adw,
       uint2* __restrict__ h2,
       float* __restrict__ as_o, float* __restrict__ ad_o) {
    constexpr int HC = H * C;
    constexpr int NT = 128;
    constexpr int XS = FIN + 8;        // half stride (bank-spread padding)
    constexpr int NTILES = HC / 8;
    constexpr int KTILES = FIN / 16;
    constexpr int QF = FIN / 4;
    constexpr int HC2 = HC / 2;

    __shared__ __half xs[NT * XS];
    __shared__ __half wt[HC * XS];

    const int tid = threadIdx.x;
    const int w = tid >> 5;
    const int lane = tid & 31;
    const int g = lane >> 2;
    const int tig = lane & 3;
    const int blockBase = blockIdx.x * NT;

    // Stage x rows (fp16, 8B chunks into padded rows).
    for (int i = tid; i < NT * QF; i += 256) {
        int l = i / QF;
        int c4 = i % QF;
        int n = blockBase + l;
        uint2 v = (n < NN) ? x2[n * QF + c4] : make_uint2(0u, 0u);
        *reinterpret_cast<uint2*>(&xs[l * XS + c4 * 4]) = v;
    }
    // Stage W transposed: wt[c][k] = (half)W[k][c].
    for (int i = tid; i < FIN * HC; i += 256) {
        int k = i / HC;
        int c = i % HC;
        wt[c * XS + k] = __float2half(Wf[i]);
    }
    __syncthreads();

    const int mbase = w * 16;
    float acc[NTILES][4];
#pragma unroll
    for (int nt = 0; nt < NTILES; nt++)
#pragma unroll
        for (int q = 0; q < 4; q++)
            acc[nt][q] = 0.0f;

#pragma unroll
    for (int kt = 0; kt < KTILES; kt++) {
        const __half* xr0 = &xs[(mbase + g) * XS + kt * 16 + 2 * tig];
        const __half* xr1 = xr0 + 8 * XS;
        unsigned a0 = *reinterpret_cast<const unsigned*>(xr0);
        unsigned a1 = *reinterpret_cast<const unsigned*>(xr1);
        unsigned a2 = *reinterpret_cast<const unsigned*>(xr0 + 8);
        unsigned a3 = *reinterpret_cast<const unsigned*>(xr1 + 8);
#pragma unroll
        for (int nt = 0; nt < NTILES; nt++) {
            const __half* wr = &wt[(nt * 8 + g) * XS + kt * 16 + 2 * tig];
            unsigned b0 = *reinterpret_cast<const unsigned*>(wr);
            unsigned b1 = *reinterpret_cast<const unsigned*>(wr + 8);
            asm volatile(
                "mma.sync.aligned.m16n8k16.row.col.f32.f16.f16.f32 "
                "{%0,%1,%2,%3}, {%4,%5,%6,%7}, {%8,%9}, {%0,%1,%2,%3};"
                : "+f"(acc[nt][0]), "+f"(acc[nt][1]),
                  "+f"(acc[nt][2]), "+f"(acc[nt][3])
                : "r"(a0), "r"(a1), "r"(a2), "r"(a3), "r"(b0), "r"(b1));
        }
    }

    // Epilogue: h2 (fp16) + alpha dots.
    const int n0 = blockBase + mbase + g;
    const int n1 = n0 + 8;
    float s0[H], sd0[H], s1[H], sd1[H];
#pragma unroll
    for (int hd = 0; hd < H; hd++) { s0[hd] = sd0[hd] = s1[hd] = sd1[hd] = 0.f; }

    __half2* hh = (__half2*)h2;
#pragma unroll
    for (int nt = 0; nt < NTILES; nt++) {
        const int c = nt * 8 + 2 * tig;
        const float aw0 = __ldg(&asw[c]), aw1 = __ldg(&asw[c + 1]);
        const float dw0 = __ldg(&adw[c]), dw1 = __ldg(&adw[c + 1]);
        const int hd = (nt * 8) / C;
        s0[hd]  += acc[nt][0] * aw0 + acc[nt][1] * aw1;
        sd0[hd] += acc[nt][0] * dw0 + acc[nt][1] * dw1;
        s1[hd]  += acc[nt][2] * aw0 + acc[nt][3] * aw1;
        sd1[hd] += acc[nt][2] * dw0 + acc[nt][3] * dw1;
        if (n0 < NN) hh[n0 * HC2 + c / 2] = __floats2half2_rn(acc[nt][0], acc[nt][1]);
        if (n1 < NN) hh[n1 * HC2 + c / 2] = __floats2half2_rn(acc[nt][2], acc[nt][3]);
    }
#pragma unroll
    for (int hd = 0; hd < H; hd++) {
        s0[hd]  += __shfl_down_sync(FULL, s0[hd], 2, 4);
        s0[hd]  += __shfl_down_sync(FULL, s0[hd], 1, 4);
        sd0[hd] += __shfl_down_sync(FULL, sd0[hd], 2, 4);
        sd0[hd] += __shfl_down_sync(FULL, sd0[hd], 1, 4);
        s1[hd]  += __shfl_down_sync(FULL, s1[hd], 2, 4);
        s1[hd]  += __shfl_down_sync(FULL, s1[hd], 1, 4);
        sd1[hd] += __shfl_down_sync(FULL, sd1[hd], 2, 4);
        sd1[hd] += __shfl_down_sync(FULL, sd1[hd], 1, 4);
    }
    if (tig == 0) {
        if (n0 < NN) {
#pragma unroll
            for (int hd = 0; hd < H; hd++) {
                as_o[n0 * H + hd] = s0[hd];
                ad_o[n0 * H + hd] = sd0[hd];
            }
        }
        if (n1 < NN) {
#pragma unroll
            for (int hd = 0; hd < H; hd++) {
                as_o[n1 * H + hd] = s1[hd];
                ad_o[n1 * H + hd] = sd1[hd];
            }
        }
    }
}

// ===========================================================================
// Aggregation H=4, C=32: warp per node, single pass, fp16 h gather + fp16 out.
// ===========================================================================
__global__ void k_agg4(const int* __restrict__ count,
                       const int* __restrict__ esrc,
                       const float4* __restrict__ as4,
                       const float4* __restrict__ ad4,
                       const uint2* __restrict__ h2,
                       const float4* __restrict__ b4,
                       uint2* __restrict__ out2) {
    __shared__ float4 sEx[8][32];
    __shared__ int sSj[8][32];
    const int n = (blockIdx.x * blockDim.x + threadIdx.x) >> 5;
    const int w = (threadIdx.x >> 5);
    const int lane = threadIdx.x & 31;
    if (n >= NN) return;
    const int hd = lane >> 3;

    const int beg = n << 6;
    const int end = beg + count[n];
    const float4 adn = __ldg(&ad4[n]);

    float4 acc = make_float4(0.f, 0.f, 0.f, 0.f);
    float4 dsum = make_float4(0.f, 0.f, 0.f, 0.f);

    for (int base = beg; base < end; base += 32) {
        const int e = base + lane;
        float4 ex = make_float4(0.f, 0.f, 0.f, 0.f);
        int s = 0;
        if (e < end) {
            s = esrc[e];
            float4 a = __ldg(&as4[s]);
            ex.x = __expf(leaky(a.x + adn.x));
            ex.y = __expf(leaky(a.y + adn.y));
            ex.z = __expf(leaky(a.z + adn.z));
            ex.w = __expf(leaky(a.w + adn.w));
        }
        dsum.x += ex.x; dsum.y += ex.y; dsum.z += ex.z; dsum.w += ex.w;
        __syncwarp();
        sEx[w][lane] = ex;
        sSj[w][lane] = s;
        __syncwarp();
        const int cnt = min(32, end - base);
#pragma unroll 2
        for (int j = 0; j < cnt; j++) {
            int sj = sSj[w][j];
            float exj = ((const float*)&sEx[w][j])[hd];
            uint2 pk = h2[sj * 32 + lane];
            unpack_fma(pk, exj, acc);
        }
    }

#pragma unroll
    for (int off = 16; off > 0; off >>= 1) {
        dsum.x += __shfl_xor_sync(FULL, dsum.x, off);
        dsum.y += __shfl_xor_sync(FULL, dsum.y, off);
        dsum.z += __shfl_xor_sync(FULL, dsum.z, off);
        dsum.w += __shfl_xor_sync(FULL, dsum.w, off);
    }
    float den = (hd == 0) ? dsum.x : (hd == 1) ? dsum.y : (hd == 2) ? dsum.z : dsum.w;
    float inv = 1.0f / (den + 1e-16f);
    float4 bb = __ldg(&b4[lane]);
    float4 o;
    o.x = fmaxf(acc.x * inv + bb.x, 0.f);
    o.y = fmaxf(acc.y * inv + bb.y, 0.f);
    o.z = fmaxf(acc.z * inv + bb.z, 0.f);
    o.w = fmaxf(acc.w * inv + bb.w, 0.f);
    out2[n * 32 + lane] = pack_h4(o);
}

// ===========================================================================
// Aggregation H=1: warp per node; OUTH=1 -> fp16 out, else fp32 out.
// ===========================================================================
template <int C, int ACT, int OUTH>
__global__ void k_agg1(const int* __restrict__ count,
                       const int* __restrict__ esrc,
                       const float* __restrict__ as,
                       const float* __restrict__ ad,
                       const uint2* __restrict__ h2,
                       const float4* __restrict__ b4,
                       void* __restrict__ outp) {
    constexpr int LPE = C / 4;
    constexpr int EPC = 32 / LPE;
    const int n = (blockIdx.x * blockDim.x + threadIdx.x) >> 5;
    const int lane = threadIdx.x & 31;
    if (n >= NN) return;
    const int sub = lane / LPE;
    const int li = lane % LPE;

    const int beg = n << 6;
    const int end = beg + count[n];
    const float adv = __ldg(&ad[n]);

    float4 acc = make_float4(0.f, 0.f, 0.f, 0.f);
    float den = 0.0f;

    for (int base = beg; base < end; base += 32) {
        const int e = base + lane;
        int s = 0;
        float ex = 0.0f;
        if (e < end) { s = esrc[e]; ex = __expf(leaky(__ldg(&as[s]) + adv)); }
        den += ex;
        const int cnt = min(32, end - base);
        for (int j = 0; j < cnt; j += EPC) {
            int jj = j + sub;
            int sj = __shfl_sync(FULL, s, jj);
            float exj = __shfl_sync(FULL, ex, jj);
            if (exj > 0.0f) {
                uint2 pk = h2[sj * LPE + li];
                unpack_fma(pk, exj, acc);
            }
        }
    }

#pragma unroll
    for (int off = 16; off > 0; off >>= 1)
        den += __shfl_xor_sync(FULL, den, off);
#pragma unroll
    for (int off = LPE; off < 32; off <<= 1) {
        acc.x += __shfl_xor_sync(FULL, acc.x, off);
        acc.y += __shfl_xor_sync(FULL, acc.y, off);
        acc.z += __shfl_xor_sync(FULL, acc.z, off);
        acc.w += __shfl_xor_sync(FULL, acc.w, off);
    }

    if (sub == 0) {
        float inv = 1.0f / (den + 1e-16f);
        float4 bb = __ldg(&b4[li]);
        float4 o;
        o.x = acc.x * inv + bb.x;
        o.y = acc.y * inv + bb.y;
        o.z = acc.z * inv + bb.z;
        o.w = acc.w * inv + bb.w;
        if (ACT == 1) {
            o.x = 1.0f / (1.0f + __expf(-o.x));
            o.y = 1.0f / (1.0f + __expf(-o.y));
            o.z = 1.0f / (1.0f + __expf(-o.z));
            o.w = 1.0f / (1.0f + __expf(-o.w));
        } else {
            o.x = fmaxf(o.x, 0.f); o.y = fmaxf(o.y, 0.f);
            o.z = fmaxf(o.z, 0.f); o.w = fmaxf(o.w, 0.f);
        }
        if (OUTH)
            ((uint2*)outp)[n * LPE + li] = pack_h4(o);
        else
            ((float4*)outp)[n * LPE + li] = o;
    }
}

extern "C" void kernel_launch(void* const* d_in, const int* in_sizes, int n_in,
                              void* d_out, int out_size) {
    const int*   node_ids = (const int*)d_in[0];
    const float* feats    = (const float*)d_in[1];
    const int*   eidx     = (const int*)d_in[2];
    const float* emb      = (const float*)d_in[4];
    const float* W1 = (const float*)d_in[5];
    const float* a1s = (const float*)d_in[6];
    const float* a1d = (const float*)d_in[7];
    const float* b1 = (const float*)d_in[8];
    const float* W2 = (const float*)d_in[9];
    const float* a2s = (const float*)d_in[10];
    const float* a2d = (const float*)d_in[11];
    const float* b2 = (const float*)d_in[12];
    const float* W3 = (const float*)d_in[13];
    const float* a3s = (const float*)d_in[14];
    const float* a3d = (const float*)d_in[15];
    const float* b3 = (const float*)d_in[16];
    const float* W4 = (const float*)d_in[17];
    const float* a4s = (const float*)d_in[18];
    const float* a4d = (const float*)d_in[19];
    const float* b4 = (const float*)d_in[20];
    float* out = (float*)d_out;

    const int E = in_sizes[2] / 2;
    const int Etot = E + NN;
    const int* src = eidx;
    const int* dst = eidx + E;

    float4 *as4, *ad4;
    uint2 *h2, *xB2, *xC2;
    int *count, *esrc;
    cudaGetSymbolAddress((void**)&h2, g_h2);
    cudaGetSymbolAddress((void**)&xB2, g_xB2);
    cudaGetSymbolAddress((void**)&xC2, g_xC2);
    cudaGetSymbolAddress((void**)&as4, g_as4);
    cudaGetSymbolAddress((void**)&ad4, g_ad4);
    cudaGetSymbolAddress((void**)&count, g_count);
    cudaGetSymbolAddress((void**)&esrc, g_esrc);
    float* as = (float*)as4;
    float* ad = (float*)ad4;

    const int T = (Etot + 7) / 8;
    const int eb = (T + 255) / 256;
    const int nwb = (NN * 32 + 255) / 256;
    const int hb = (NN + 127) / 128;   // hmma grid (NT=128)

    // Side stream: slot-CSR, overlapped with layer-1 GEMM.
    cudaStream_t s2;
    cudaStreamCreateWithFlags(&s2, cudaStreamNonBlocking);
    cudaEvent_t evA, evB;
    cudaEventCreateWithFlags(&evA, cudaEventDisableTiming);
    cudaEventCreateWithFlags(&evB, cudaEventDisableTiming);

    cudaEventRecord(evA, 0);
    cudaStreamWaitEvent(s2, evA, 0);

    cudaMemsetAsync(count, 0, NN * sizeof(int), s2);
    k_scatter<<<eb, 256, 0, s2>>>(src, dst, E, Etot, T, count, esrc);
    cudaEventRecord(evB, s2);

    // ---- Layer 1: 23 -> 4x32 (overlaps CSR build) ----
    k_mm1<<<(NN + 63) / 64, 256>>>(node_ids, feats, emb, (const float4*)W1,
                                   (const float4*)a1s, (const float4*)a1d,
                                   h2, as, ad);
    cudaStreamWaitEvent(0, evB, 0);
    k_agg4<<<nwb, 256>>>(count, esrc, as4, ad4, h2, (const float4*)b1, xB2);

    // ---- Layer 2: 128 -> 1x32 (tensor cores) ----
    k_hmma<128, 1, 32><<<hb, 256>>>(xB2, W2, a2s, a2d, h2, as, ad);
    k_agg1<32, 0, 1><<<nwb, 256>>>(count, esrc, as, ad, h2, (const float4*)b2, xC2);

    // ---- Layer 3: 32 -> 4x32 (tensor cores) ----
    k_hmma<32, 4, 32><<<hb, 256>>>(xC2, W3, a3s, a3d, h2, as, ad);
    k_agg4<<<nwb, 256>>>(count, esrc, as4, ad4, h2, (const float4*)b3, xB2);

    // ---- Layer 4: 128 -> 1x16, sigmoid (tensor cores) ----
    k_hmma<128, 1, 16><<<hb, 256>>>(xB2, W4, a4s, a4d, h2, as, ad);
    k_agg1<16, 1, 0><<<nwb, 256>>>(count, esrc, as, ad, h2, (const float4*)b4, out);
}